// round 1
// baseline (speedup 1.0000x reference)
#include <cuda_runtime.h>

#define Nn 50000
#define Ee 400000
#define Kk 512
#define Hh 8
#define Ff 64
#define HFt 512
#define NEG 0.2f

// ---------------- device scratch (allowed per rules) ----------------
__device__ float g_featv[Nn * HFt];   // 102.4 MB: feat @ W_val + b_val
__device__ float g_el[Nn * Hh];
__device__ float g_er[Nn * Hh];
__device__ float g_u[Kk * 16];        // cols 0..7 = u_l, 8..15 = u_r
__device__ float g_c[16];             // folded bias terms
__device__ int   g_deg[Nn];
__device__ int   g_row[Nn + 1];
__device__ int   g_pos[Nn];
__device__ int   g_csrc[Ee];          // CSR by dst: src indices

// ---------------- fold attn vectors into weights ----------------
__global__ void k_prep(const float* __restrict__ Wsrc, const float* __restrict__ Wdst,
                       const float* __restrict__ al, const float* __restrict__ ar,
                       const float* __restrict__ bsrc, const float* __restrict__ bdst) {
    int id = blockIdx.x * blockDim.x + threadIdx.x;
    if (id < Kk * 16) {
        int k = id >> 4, j = id & 15, h = j & 7;
        const float* W = (j < 8) ? Wsrc : Wdst;
        const float* a = (j < 8) ? al : ar;
        float s = 0.f;
        #pragma unroll 8
        for (int f = 0; f < Ff; f++) s += W[k * HFt + h * Ff + f] * a[h * Ff + f];
        g_u[k * 16 + j] = s;
    }
    if (blockIdx.x == 0 && threadIdx.x < 16) {
        int j = threadIdx.x, h = j & 7;
        const float* b = (j < 8) ? bsrc : bdst;
        const float* a = (j < 8) ? al : ar;
        float s = 0.f;
        for (int f = 0; f < Ff; f++) s += b[h * Ff + f] * a[h * Ff + f];
        g_c[j] = s;
    }
}

__global__ void k_zero_deg() {
    int i = blockIdx.x * blockDim.x + threadIdx.x;
    if (i < Nn) g_deg[i] = 0;
}

__global__ void k_hist(const int* __restrict__ dst) {
    int e = blockIdx.x * blockDim.x + threadIdx.x;
    if (e < Ee) atomicAdd(&g_deg[dst[e]], 1);
}

// single-block exclusive scan over g_deg -> g_row, g_pos
__global__ void k_scan() {
    __shared__ int sh[1024];
    __shared__ int s_carry;
    int t = threadIdx.x;
    if (t == 0) s_carry = 0;
    __syncthreads();
    for (int base = 0; base < Nn; base += 1024) {
        int v = (base + t < Nn) ? g_deg[base + t] : 0;
        sh[t] = v;
        __syncthreads();
        for (int off = 1; off < 1024; off <<= 1) {
            int x = (t >= off) ? sh[t - off] : 0;
            __syncthreads();
            sh[t] += x;
            __syncthreads();
        }
        int excl = s_carry + sh[t] - v;
        if (base + t < Nn) { g_row[base + t] = excl; g_pos[base + t] = excl; }
        __syncthreads();
        if (t == 0) s_carry += sh[1023];
        __syncthreads();
    }
    if (t == 0) g_row[Nn] = s_carry;
}

__global__ void k_scatter(const int* __restrict__ src, const int* __restrict__ dst) {
    int e = blockIdx.x * blockDim.x + threadIdx.x;
    if (e < Ee) {
        int d = dst[e];
        int slot = atomicAdd(&g_pos[d], 1);
        g_csrc[slot] = src[e];
    }
}

// ---------------- skinny GEMM: el/er = feat @ u + c ----------------
__global__ void __launch_bounds__(128) k_elr(const float* __restrict__ feat) {
    __shared__ float sA[128][33];
    __shared__ float sB[32][16];
    int tid = threadIdx.x;
    int rowBase = blockIdx.x * 128;
    float acc[16];
    #pragma unroll
    for (int j = 0; j < 16; j++) acc[j] = g_c[j];

    for (int kt = 0; kt < Kk; kt += 32) {
        #pragma unroll
        for (int i = 0; i < 8; i++) {
            int f4 = i * 128 + tid;
            int r = f4 >> 3, c4 = f4 & 7;
            int gr = rowBase + r;
            float4 v = make_float4(0.f, 0.f, 0.f, 0.f);
            if (gr < Nn) v = *(const float4*)&feat[gr * Kk + kt + c4 * 4];
            sA[r][c4 * 4 + 0] = v.x; sA[r][c4 * 4 + 1] = v.y;
            sA[r][c4 * 4 + 2] = v.z; sA[r][c4 * 4 + 3] = v.w;
        }
        {
            int r = tid >> 2, c4 = tid & 3;
            float4 v = *(const float4*)&g_u[(kt + r) * 16 + c4 * 4];
            *(float4*)&sB[r][c4 * 4] = v;
        }
        __syncthreads();
        #pragma unroll
        for (int k = 0; k < 32; k++) {
            float f = sA[tid][k];
            float4 b0 = *(float4*)&sB[k][0];
            float4 b1 = *(float4*)&sB[k][4];
            float4 b2 = *(float4*)&sB[k][8];
            float4 b3 = *(float4*)&sB[k][12];
            acc[0] += f * b0.x; acc[1] += f * b0.y; acc[2] += f * b0.z; acc[3] += f * b0.w;
            acc[4] += f * b1.x; acc[5] += f * b1.y; acc[6] += f * b1.z; acc[7] += f * b1.w;
            acc[8] += f * b2.x; acc[9] += f * b2.y; acc[10] += f * b2.z; acc[11] += f * b2.w;
            acc[12] += f * b3.x; acc[13] += f * b3.y; acc[14] += f * b3.z; acc[15] += f * b3.w;
        }
        __syncthreads();
    }
    int n = rowBase + tid;
    if (n < Nn) {
        #pragma unroll
        for (int h = 0; h < 8; h++) {
            g_el[n * 8 + h] = acc[h];
            g_er[n * 8 + h] = acc[8 + h];
        }
    }
}

// ---------------- main GEMM: featv = feat @ W_val + b_val ----------------
__global__ void __launch_bounds__(256) k_gemm(const float* __restrict__ A,
                                              const float* __restrict__ B,
                                              const float* __restrict__ bias) {
    __shared__ float As[8][132];
    __shared__ float Bs[8][128];
    int tid = threadIdx.x;
    int rowBase = blockIdx.y * 128, colBase = blockIdx.x * 128;
    int tx = tid & 15, ty = tid >> 4;
    float acc[8][8];
    #pragma unroll
    for (int i = 0; i < 8; i++)
        #pragma unroll
        for (int j = 0; j < 8; j++) acc[i][j] = 0.f;

    int arow = tid >> 1, aseg = tid & 1;
    int brow = tid >> 5, bcol4 = tid & 31;
    bool arow_ok = (rowBase + arow) < Nn;
    const float* Ap = A + (size_t)(rowBase + arow) * Kk + aseg * 4;
    const float* Bp = B + (size_t)brow * HFt + colBase + bcol4 * 4;

    float4 av = arow_ok ? *(const float4*)(Ap) : make_float4(0.f, 0.f, 0.f, 0.f);
    float4 bv = *(const float4*)(Bp);

    for (int kt = 0; kt < Kk; kt += 8) {
        As[aseg * 4 + 0][arow] = av.x; As[aseg * 4 + 1][arow] = av.y;
        As[aseg * 4 + 2][arow] = av.z; As[aseg * 4 + 3][arow] = av.w;
        *(float4*)&Bs[brow][bcol4 * 4] = bv;
        __syncthreads();
        if (kt + 8 < Kk) {
            av = arow_ok ? *(const float4*)(Ap + kt + 8) : make_float4(0.f, 0.f, 0.f, 0.f);
            bv = *(const float4*)(Bp + (size_t)(kt + 8) * HFt);
        }
        #pragma unroll
        for (int k = 0; k < 8; k++) {
            float ra[8], rb[8];
            *(float4*)&ra[0] = *(float4*)&As[k][ty * 8];
            *(float4*)&ra[4] = *(float4*)&As[k][ty * 8 + 4];
            *(float4*)&rb[0] = *(float4*)&Bs[k][tx * 8];
            *(float4*)&rb[4] = *(float4*)&Bs[k][tx * 8 + 4];
            #pragma unroll
            for (int i = 0; i < 8; i++)
                #pragma unroll
                for (int j = 0; j < 8; j++) acc[i][j] += ra[i] * rb[j];
        }
        __syncthreads();
    }
    #pragma unroll
    for (int i = 0; i < 8; i++) {
        int r = rowBase + ty * 8 + i;
        if (r < Nn) {
            #pragma unroll
            for (int j = 0; j < 8; j += 4) {
                int c = colBase + tx * 8 + j;
                float4 o;
                o.x = acc[i][j + 0] + bias[c + 0];
                o.y = acc[i][j + 1] + bias[c + 1];
                o.z = acc[i][j + 2] + bias[c + 2];
                o.w = acc[i][j + 3] + bias[c + 3];
                *(float4*)&g_featv[(size_t)r * HFt + c] = o;
            }
        }
    }
}

// ---------------- per-dst softmax + aggregation (one block / node) ----------------
#define CH 256
__global__ void __launch_bounds__(512) k_agg(float* __restrict__ out) {
    int n = blockIdx.x;
    int tid = threadIdx.x;
    __shared__ float er_sh[8], mx_sh[8], rs_sh[8];
    __shared__ float red[64];
    __shared__ float a_sh[CH][8];
    __shared__ int s_sh[CH];

    int beg = g_row[n], end = g_row[n + 1];
    if (tid < 8) er_sh[tid] = g_er[n * 8 + tid];
    __syncthreads();

    // pass 1: per-head max over incident edges
    if (tid < 64) {
        int h = tid & 7, jj = tid >> 3;
        float m = -1e30f;
        for (int j = beg + jj; j < end; j += 8) {
            int s = g_csrc[j];
            float e = g_el[s * 8 + h] + er_sh[h];
            e = (e >= 0.f) ? e : NEG * e;
            m = fmaxf(m, e);
        }
        red[tid] = m;
    }
    __syncthreads();
    if (tid < 8) {
        float m = red[tid];
        #pragma unroll
        for (int jj = 1; jj < 8; jj++) m = fmaxf(m, red[jj * 8 + tid]);
        mx_sh[tid] = m;
    }
    __syncthreads();

    // pass 2: per-head sum of exp
    if (tid < 64) {
        int h = tid & 7, jj = tid >> 3;
        float m = mx_sh[h], ssum = 0.f;
        for (int j = beg + jj; j < end; j += 8) {
            int s = g_csrc[j];
            float e = g_el[s * 8 + h] + er_sh[h];
            e = (e >= 0.f) ? e : NEG * e;
            ssum += __expf(e - m);
        }
        red[tid] = ssum;
    }
    __syncthreads();
    if (tid < 8) {
        float ssum = 0.f;
        #pragma unroll
        for (int jj = 0; jj < 8; jj++) ssum += red[jj * 8 + tid];
        rs_sh[tid] = 1.0f / fmaxf(ssum, 1e-16f);
    }
    __syncthreads();

    // pass 3: weighted aggregation; thread owns output col tid (h = tid/64)
    float acc = 0.f;
    int h = tid >> 6;
    for (int cbeg = beg; cbeg < end; cbeg += CH) {
        int clen = min(CH, end - cbeg);
        for (int j = tid; j < clen; j += 512) s_sh[j] = g_csrc[cbeg + j];
        __syncthreads();
        for (int t = tid; t < clen * 8; t += 512) {
            int jl = t >> 3, hh = t & 7;
            float e = g_el[s_sh[jl] * 8 + hh] + er_sh[hh];
            e = (e >= 0.f) ? e : NEG * e;
            a_sh[jl][hh] = __expf(e - mx_sh[hh]) * rs_sh[hh];
        }
        __syncthreads();
        #pragma unroll 4
        for (int jl = 0; jl < clen; jl++) {
            acc += a_sh[jl][h] * g_featv[(size_t)s_sh[jl] * HFt + tid];
        }
        __syncthreads();
    }
    out[(size_t)n * HFt + tid] = acc;
}

// ---------------- launch ----------------
extern "C" void kernel_launch(void* const* d_in, const int* in_sizes, int n_in,
                              void* d_out, int out_size) {
    const float* feat = (const float*)d_in[0];
    const int*   src  = (const int*)d_in[1];
    const int*   dst  = (const int*)d_in[2];
    const float* Wsrc = (const float*)d_in[3];
    const float* bsrc = (const float*)d_in[4];
    const float* Wdst = (const float*)d_in[5];
    const float* bdst = (const float*)d_in[6];
    const float* Wval = (const float*)d_in[7];
    const float* bval = (const float*)d_in[8];
    const float* al   = (const float*)d_in[9];
    const float* ar   = (const float*)d_in[10];
    float* out = (float*)d_out;

    k_prep<<<32, 256>>>(Wsrc, Wdst, al, ar, bsrc, bdst);
    k_zero_deg<<<(Nn + 255) / 256, 256>>>();
    k_hist<<<(Ee + 255) / 256, 256>>>(dst);
    k_scan<<<1, 1024>>>();
    k_scatter<<<(Ee + 255) / 256, 256>>>(src, dst);
    k_elr<<<(Nn + 127) / 128, 128>>>(feat);
    dim3 g(HFt / 128, (Nn + 127) / 128);
    k_gemm<<<g, 256>>>(feat, Wval, bval);
    k_agg<<<Nn, 512>>>(out);
}

// round 3
// speedup vs baseline: 1.3574x; 1.3574x over previous
#include <cuda_runtime.h>
#include <cuda_bf16.h>
#include <cstdint>

#define Nn 50000
#define NnP 50048
#define Ee 400000
#define Kk 512
#define Hh 8
#define Ff 64
#define HFt 512
#define NEG 0.2f

// ---------------- device scratch ----------------
__device__ __align__(16) float g_featv[Nn * HFt];            // 102.4 MB
__device__ __align__(16) __nv_bfloat16 g_Ah[(size_t)NnP * Kk];
__device__ __align__(16) __nv_bfloat16 g_Al[(size_t)NnP * Kk];
__device__ __align__(16) __nv_bfloat16 g_Bh[HFt * Kk];       // W_val^T hi  [N][K]
__device__ __align__(16) __nv_bfloat16 g_Bl[HFt * Kk];       // W_val^T lo
__device__ float g_el[Nn * Hh];
__device__ float g_er[Nn * Hh];
__device__ float g_u[Kk * 16];
__device__ float g_c[16];
__device__ int   g_deg[Nn];
__device__ int   g_row[Nn + 1];
__device__ int   g_pos[Nn];
__device__ int   g_csrc[Ee];
__device__ int   g_part[64];
__device__ int   g_poff[64];

// ---------------- ptx helpers ----------------
__device__ __forceinline__ uint32_t smem_u32(const void* p) {
    uint32_t a;
    asm("{ .reg .u64 t; cvta.to.shared.u64 t, %1; cvt.u32.u64 %0, t; }" : "=r"(a) : "l"(p));
    return a;
}
__device__ __forceinline__ void cpa16(uint32_t d, const void* s) {
    asm volatile("cp.async.cg.shared.global [%0], [%1], 16;" :: "r"(d), "l"(s));
}
__device__ __forceinline__ void cp_commit() {
    asm volatile("cp.async.commit_group;" ::: "memory");
}
template<int NN>
__device__ __forceinline__ void cp_wait() {
    asm volatile("cp.async.wait_group %0;" :: "n"(NN) : "memory");
}
__device__ __forceinline__ void ldmx4(uint32_t& r0, uint32_t& r1, uint32_t& r2, uint32_t& r3, uint32_t a) {
    asm volatile("ldmatrix.sync.aligned.m8n8.x4.shared.b16 {%0,%1,%2,%3}, [%4];"
                 : "=r"(r0), "=r"(r1), "=r"(r2), "=r"(r3) : "r"(a));
}
__device__ __forceinline__ void mma16816(float* d, const uint32_t* a, uint32_t b0, uint32_t b1) {
    asm volatile("mma.sync.aligned.m16n8k16.row.col.f32.bf16.bf16.f32 "
                 "{%0,%1,%2,%3}, {%4,%5,%6,%7}, {%8,%9}, {%0,%1,%2,%3};"
                 : "+f"(d[0]), "+f"(d[1]), "+f"(d[2]), "+f"(d[3])
                 : "r"(a[0]), "r"(a[1]), "r"(a[2]), "r"(a[3]), "r"(b0), "r"(b1));
}

// ---------------- fold attn vectors into weights ----------------
__global__ void k_prep(const float* __restrict__ Wsrc, const float* __restrict__ Wdst,
                       const float* __restrict__ al, const float* __restrict__ ar,
                       const float* __restrict__ bsrc, const float* __restrict__ bdst) {
    int id = blockIdx.x * blockDim.x + threadIdx.x;
    if (id < Kk * 16) {
        int k = id >> 4, j = id & 15, h = j & 7;
        const float* W = (j < 8) ? Wsrc : Wdst;
        const float* a = (j < 8) ? al : ar;
        float s = 0.f;
        #pragma unroll 8
        for (int f = 0; f < Ff; f++) s += W[k * HFt + h * Ff + f] * a[h * Ff + f];
        g_u[k * 16 + j] = s;
    }
    if (blockIdx.x == 0 && threadIdx.x < 16) {
        int j = threadIdx.x, h = j & 7;
        const float* b = (j < 8) ? bsrc : bdst;
        const float* a = (j < 8) ? al : ar;
        float s = 0.f;
        for (int f = 0; f < Ff; f++) s += b[h * Ff + f] * a[h * Ff + f];
        g_c[j] = s;
    }
}

__global__ void k_zero_deg() {
    int i = blockIdx.x * blockDim.x + threadIdx.x;
    if (i < Nn) g_deg[i] = 0;
}

__global__ void k_hist(const int* __restrict__ dst) {
    int e = blockIdx.x * blockDim.x + threadIdx.x;
    if (e < Ee) atomicAdd(&g_deg[dst[e]], 1);
}

// ---------------- 3-phase scan ----------------
__global__ void k_scan1() {
    __shared__ int sh[1024];
    int t = threadIdx.x;
    int i = blockIdx.x * 1024 + t;
    int v = (i < Nn) ? g_deg[i] : 0;
    sh[t] = v;
    __syncthreads();
    for (int off = 1; off < 1024; off <<= 1) {
        int x = (t >= off) ? sh[t - off] : 0;
        __syncthreads();
        sh[t] += x;
        __syncthreads();
    }
    if (i < Nn) g_row[i] = sh[t] - v;
    if (t == 1023) g_part[blockIdx.x] = sh[1023];
}
__global__ void k_scan2(int nblk) {
    if (threadIdx.x == 0) {
        int run = 0;
        for (int b = 0; b < nblk; b++) { g_poff[b] = run; run += g_part[b]; }
        g_row[Nn] = run;
    }
}
__global__ void k_scan3() {
    int i = blockIdx.x * 1024 + threadIdx.x;
    if (i < Nn) {
        int x = g_row[i] + g_poff[blockIdx.x];
        g_row[i] = x;
        g_pos[i] = x;
    }
}

__global__ void k_scatter(const int* __restrict__ src, const int* __restrict__ dst) {
    int e = blockIdx.x * blockDim.x + threadIdx.x;
    if (e < Ee) {
        int d = dst[e];
        int slot = atomicAdd(&g_pos[d], 1);
        g_csrc[slot] = src[e];
    }
}

// ---------------- feat -> bf16 hi/lo split (padded rows zeroed) ----------------
__global__ void __launch_bounds__(256) k_convert(const float* __restrict__ feat) {
    size_t idx = (size_t)blockIdx.x * 256 + threadIdx.x;   // one float4
    size_t row = idx >> 7;                                  // 128 quads per row
    float4 v = make_float4(0.f, 0.f, 0.f, 0.f);
    if (row < Nn) v = ((const float4*)feat)[idx];
    float x[4] = {v.x, v.y, v.z, v.w};
    unsigned short hs[4], ls[4];
    #pragma unroll
    for (int i = 0; i < 4; i++) {
        __nv_bfloat16 h = __float2bfloat16(x[i]);
        float hf = __bfloat162float(h);
        __nv_bfloat16 l = __float2bfloat16(x[i] - hf);
        hs[i] = *reinterpret_cast<unsigned short*>(&h);
        ls[i] = *reinterpret_cast<unsigned short*>(&l);
    }
    uint2 hp = make_uint2((uint32_t)hs[0] | ((uint32_t)hs[1] << 16),
                          (uint32_t)hs[2] | ((uint32_t)hs[3] << 16));
    uint2 lp = make_uint2((uint32_t)ls[0] | ((uint32_t)ls[1] << 16),
                          (uint32_t)ls[2] | ((uint32_t)ls[3] << 16));
    ((uint2*)g_Ah)[idx] = hp;
    ((uint2*)g_Al)[idx] = lp;
}

// ---------------- W_val -> transposed bf16 hi/lo ----------------
__global__ void k_wconv(const float* __restrict__ W) {
    int idx = blockIdx.x * 256 + threadIdx.x;   // [n][k]
    if (idx < HFt * Kk) {
        int n = idx >> 9, k = idx & 511;
        float x = W[k * HFt + n];
        __nv_bfloat16 h = __float2bfloat16(x);
        float hf = __bfloat162float(h);
        g_Bh[idx] = h;
        g_Bl[idx] = __float2bfloat16(x - hf);
    }
}

// ---------------- skinny GEMM: el/er = feat @ u + c ----------------
__global__ void __launch_bounds__(128) k_elr(const float* __restrict__ feat) {
    __shared__ float sA[128][33];
    __shared__ float sB[32][16];
    int tid = threadIdx.x;
    int rowBase = blockIdx.x * 128;
    float acc[16];
    #pragma unroll
    for (int j = 0; j < 16; j++) acc[j] = g_c[j];

    for (int kt = 0; kt < Kk; kt += 32) {
        #pragma unroll
        for (int i = 0; i < 8; i++) {
            int f4 = i * 128 + tid;
            int r = f4 >> 3, c4 = f4 & 7;
            int gr = rowBase + r;
            float4 v = make_float4(0.f, 0.f, 0.f, 0.f);
            if (gr < Nn) v = *(const float4*)&feat[gr * Kk + kt + c4 * 4];
            sA[r][c4 * 4 + 0] = v.x; sA[r][c4 * 4 + 1] = v.y;
            sA[r][c4 * 4 + 2] = v.z; sA[r][c4 * 4 + 3] = v.w;
        }
        {
            int r = tid >> 2, c4 = tid & 3;
            float4 v = *(const float4*)&g_u[(kt + r) * 16 + c4 * 4];
            *(float4*)&sB[r][c4 * 4] = v;
        }
        __syncthreads();
        #pragma unroll
        for (int k = 0; k < 32; k++) {
            float f = sA[tid][k];
            float4 b0 = *(float4*)&sB[k][0];
            float4 b1 = *(float4*)&sB[k][4];
            float4 b2 = *(float4*)&sB[k][8];
            float4 b3 = *(float4*)&sB[k][12];
            acc[0] += f * b0.x; acc[1] += f * b0.y; acc[2] += f * b0.z; acc[3] += f * b0.w;
            acc[4] += f * b1.x; acc[5] += f * b1.y; acc[6] += f * b1.z; acc[7] += f * b1.w;
            acc[8] += f * b2.x; acc[9] += f * b2.y; acc[10] += f * b2.z; acc[11] += f * b2.w;
            acc[12] += f * b3.x; acc[13] += f * b3.y; acc[14] += f * b3.z; acc[15] += f * b3.w;
        }
        __syncthreads();
    }
    int n = rowBase + tid;
    if (n < Nn) {
        #pragma unroll
        for (int h = 0; h < 8; h++) {
            g_el[n * 8 + h] = acc[h];
            g_er[n * 8 + h] = acc[8 + h];
        }
    }
}

// ---------------- HMMA GEMM: featv = feat @ W_val + b_val ----------------
// bf16 split: D = Ah*Bh + Ah*Bl + Al*Bh, fp32 accumulate (mma.sync m16n8k16).
// CTA tile 128x128, BK=32, 8 warps (warp tile 32x64), cp.async double buffer.
#define PITCH 80                       // smem row pitch bytes (conflict-free ldmatrix)
#define MAT_B (128 * PITCH)            // 10240 bytes per matrix tile
#define STAGE_B (4 * MAT_B)            // Ah, Al, Bh, Bl
#define SMEM_GEMM (2 * STAGE_B)        // 81920

__global__ void __launch_bounds__(256, 1) k_gemm_mma(const float* __restrict__ bias) {
    extern __shared__ char sm[];
    uint32_t sb = smem_u32(sm);

    const int tid = threadIdx.x;
    const int lane = tid & 31, wid = tid >> 5;
    const int wm = wid >> 1, wn = wid & 1;           // warp grid 4x2
    const int mBase = blockIdx.y * 128;
    const int nBase = blockIdx.x * 128;

    // ---- load thread mapping: 4 matrices x 64 threads, 8 x 16B each ----
    const int mat = tid >> 6;          // 0=Ah 1=Al 2=Bh 3=Bl
    const int t64 = tid & 63;
    const __nv_bfloat16* gsrc;
    int rowBaseG;
    if (mat == 0)      { gsrc = g_Ah; rowBaseG = mBase; }
    else if (mat == 1) { gsrc = g_Al; rowBaseG = mBase; }
    else if (mat == 2) { gsrc = g_Bh; rowBaseG = nBase; }
    else               { gsrc = g_Bl; rowBaseG = nBase; }
    const uint32_t smatBase = sb + mat * MAT_B;

    // ---- ldmatrix address precompute ----
    const int g8 = lane >> 3, lr = lane & 7;
    const int a_row = lr + ((g8 == 1 || g8 == 3) ? 8 : 0);
    const uint32_t a_kb = (g8 >= 2) ? 16 : 0;
    const int b_row = lr + ((g8 >= 2) ? 8 : 0);
    const uint32_t b_kb = (g8 & 1) ? 16 : 0;
    const uint32_t aAddr0 = sb + 0 * MAT_B + (wm * 32 + a_row) * PITCH + a_kb; // Ah
    const uint32_t aAddr1 = sb + 1 * MAT_B + (wm * 32 + a_row) * PITCH + a_kb; // Al
    const uint32_t bAddr0 = sb + 2 * MAT_B + (wn * 64 + b_row) * PITCH + b_kb; // Bh
    const uint32_t bAddr1 = sb + 3 * MAT_B + (wn * 64 + b_row) * PITCH + b_kb; // Bl

    float acc[2][8][4];
    #pragma unroll
    for (int i = 0; i < 2; i++)
        #pragma unroll
        for (int j = 0; j < 8; j++)
            #pragma unroll
            for (int q = 0; q < 4; q++) acc[i][j][q] = 0.f;

    // ---- stage loader ----
    auto load_stage = [&](int c, int buf) {
        uint32_t dstB = smatBase + buf * STAGE_B;
        const __nv_bfloat16* gp = gsrc + (size_t)rowBaseG * Kk + c * 32;
        #pragma unroll
        for (int i = 0; i < 8; i++) {
            int idx = t64 * 8 + i;
            int r = idx >> 2, ch = idx & 3;
            cpa16(dstB + r * PITCH + ch * 16, gp + (size_t)r * Kk + ch * 8);
        }
    };

    load_stage(0, 0);
    cp_commit();

    for (int c = 0; c < 16; c++) {
        if (c + 1 < 16) {
            load_stage(c + 1, (c + 1) & 1);
            cp_commit();
            cp_wait<1>();
        } else {
            cp_wait<0>();
        }
        __syncthreads();

        const uint32_t stOff = (c & 1) * STAGE_B;
        #pragma unroll
        for (int ks = 0; ks < 2; ks++) {
            uint32_t kb = stOff + ks * 32;
            uint32_t ah[2][4], al[2][4], bh[4][4], bl[4][4];
            #pragma unroll
            for (int mt = 0; mt < 2; mt++) {
                ldmx4(ah[mt][0], ah[mt][1], ah[mt][2], ah[mt][3], aAddr0 + kb + mt * 16 * PITCH);
                ldmx4(al[mt][0], al[mt][1], al[mt][2], al[mt][3], aAddr1 + kb + mt * 16 * PITCH);
            }
            #pragma unroll
            for (int nt = 0; nt < 4; nt++) {
                ldmx4(bh[nt][0], bh[nt][1], bh[nt][2], bh[nt][3], bAddr0 + kb + nt * 16 * PITCH);
                ldmx4(bl[nt][0], bl[nt][1], bl[nt][2], bl[nt][3], bAddr1 + kb + nt * 16 * PITCH);
            }
            #pragma unroll
            for (int mt = 0; mt < 2; mt++)
                #pragma unroll
                for (int nt = 0; nt < 4; nt++) {
                    mma16816(acc[mt][2 * nt + 0], ah[mt], bh[nt][0], bh[nt][1]);
                    mma16816(acc[mt][2 * nt + 1], ah[mt], bh[nt][2], bh[nt][3]);
                    mma16816(acc[mt][2 * nt + 0], ah[mt], bl[nt][0], bl[nt][1]);
                    mma16816(acc[mt][2 * nt + 1], ah[mt], bl[nt][2], bl[nt][3]);
                    mma16816(acc[mt][2 * nt + 0], al[mt], bh[nt][0], bh[nt][1]);
                    mma16816(acc[mt][2 * nt + 1], al[mt], bh[nt][2], bh[nt][3]);
                }
        }
        __syncthreads();
    }

    // ---- epilogue: direct stores with bias ----
    const int qr = lane >> 2, qc = (lane & 3) * 2;
    #pragma unroll
    for (int mt = 0; mt < 2; mt++) {
        int row0 = mBase + wm * 32 + mt * 16 + qr;
        #pragma unroll
        for (int n8 = 0; n8 < 8; n8++) {
            int col = nBase + wn * 64 + n8 * 8 + qc;
            float bx = bias[col], by = bias[col + 1];
            if (row0 < Nn) {
                float2 o = make_float2(acc[mt][n8][0] + bx, acc[mt][n8][1] + by);
                *(float2*)&g_featv[(size_t)row0 * HFt + col] = o;
            }
            if (row0 + 8 < Nn) {
                float2 o = make_float2(acc[mt][n8][2] + bx, acc[mt][n8][3] + by);
                *(float2*)&g_featv[(size_t)(row0 + 8) * HFt + col] = o;
            }
        }
    }
}

// ---------------- per-dst softmax + aggregation ----------------
#define CH 256
__global__ void __launch_bounds__(512) k_agg(float* __restrict__ out) {
    int n = blockIdx.x;
    int tid = threadIdx.x;
    __shared__ float er_sh[8], mx_sh[8], rs_sh[8];
    __shared__ float red[64];
    __shared__ float a_sh[CH][8];
    __shared__ int s_sh[CH];

    int beg = g_row[n], end = g_row[n + 1];
    if (tid < 8) er_sh[tid] = g_er[n * 8 + tid];
    __syncthreads();

    if (tid < 64) {
        int h = tid & 7, jj = tid >> 3;
        float m = -1e30f;
        for (int j = beg + jj; j < end; j += 8) {
            int s = g_csrc[j];
            float e = g_el[s * 8 + h] + er_sh[h];
            e = (e >= 0.f) ? e : NEG * e;
            m = fmaxf(m, e);
        }
        red[tid] = m;
    }
    __syncthreads();
    if (tid < 8) {
        float m = red[tid];
        #pragma unroll
        for (int jj = 1; jj < 8; jj++) m = fmaxf(m, red[jj * 8 + tid]);
        mx_sh[tid] = m;
    }
    __syncthreads();

    if (tid < 64) {
        int h = tid & 7, jj = tid >> 3;
        float m = mx_sh[h], ssum = 0.f;
        for (int j = beg + jj; j < end; j += 8) {
            int s = g_csrc[j];
            float e = g_el[s * 8 + h] + er_sh[h];
            e = (e >= 0.f) ? e : NEG * e;
            ssum += __expf(e - m);
        }
        red[tid] = ssum;
    }
    __syncthreads();
    if (tid < 8) {
        float ssum = 0.f;
        #pragma unroll
        for (int jj = 0; jj < 8; jj++) ssum += red[jj * 8 + tid];
        rs_sh[tid] = 1.0f / fmaxf(ssum, 1e-16f);
    }
    __syncthreads();

    float acc = 0.f;
    int h = tid >> 6;
    for (int cbeg = beg; cbeg < end; cbeg += CH) {
        int clen = min(CH, end - cbeg);
        for (int j = tid; j < clen; j += 512) s_sh[j] = g_csrc[cbeg + j];
        __syncthreads();
        for (int t = tid; t < clen * 8; t += 512) {
            int jl = t >> 3, hh = t & 7;
            float e = g_el[s_sh[jl] * 8 + hh] + er_sh[hh];
            e = (e >= 0.f) ? e : NEG * e;
            a_sh[jl][hh] = __expf(e - mx_sh[hh]) * rs_sh[hh];
        }
        __syncthreads();
        #pragma unroll 4
        for (int jl = 0; jl < clen; jl++) {
            acc += a_sh[jl][h] * g_featv[(size_t)s_sh[jl] * HFt + tid];
        }
        __syncthreads();
    }
    out[(size_t)n * HFt + tid] = acc;
}

// ---------------- launch ----------------
extern "C" void kernel_launch(void* const* d_in, const int* in_sizes, int n_in,
                              void* d_out, int out_size) {
    const float* feat = (const float*)d_in[0];
    const int*   src  = (const int*)d_in[1];
    const int*   dst  = (const int*)d_in[2];
    const float* Wsrc = (const float*)d_in[3];
    const float* bsrc = (const float*)d_in[4];
    const float* Wdst = (const float*)d_in[5];
    const float* bdst = (const float*)d_in[6];
    const float* Wval = (const float*)d_in[7];
    const float* bval = (const float*)d_in[8];
    const float* al   = (const float*)d_in[9];
    const float* ar   = (const float*)d_in[10];
    float* out = (float*)d_out;

    static bool attr_set = false;
    if (!attr_set) {
        cudaFuncSetAttribute(k_gemm_mma, cudaFuncAttributeMaxDynamicSharedMemorySize, SMEM_GEMM);
        attr_set = true;
    }

    int nscan = (Nn + 1023) / 1024;
    k_prep<<<32, 256>>>(Wsrc, Wdst, al, ar, bsrc, bdst);
    k_zero_deg<<<(Nn + 255) / 256, 256>>>();
    k_hist<<<(Ee + 255) / 256, 256>>>(dst);
    k_scan1<<<nscan, 1024>>>();
    k_scan2<<<1, 32>>>(nscan);
    k_scan3<<<nscan, 1024>>>();
    k_scatter<<<(Ee + 255) / 256, 256>>>(src, dst);
    k_convert<<<(NnP * Kk / 4) / 256, 256>>>(feat);
    k_wconv<<<(HFt * Kk + 255) / 256, 256>>>(Wval);
    k_elr<<<(Nn + 127) / 128, 128>>>(feat);
    dim3 gg(HFt / 128, NnP / 128);
    k_gemm_mma<<<gg, 256, SMEM_GEMM>>>(bval);
    k_agg<<<Nn, 512>>>(out);
}

// round 4
// speedup vs baseline: 1.8266x; 1.3457x over previous
#include <cuda_runtime.h>
#include <cuda_bf16.h>
#include <cstdint>

#define Nn 50000
#define NnP 50048
#define Ee 400000
#define Kk 512
#define Hh 8
#define Ff 64
#define HFt 512
#define NEG 0.2f

// ---------------- device scratch ----------------
__device__ __align__(16) float g_featv[Nn * HFt];            // 102.4 MB
__device__ __align__(16) __nv_bfloat16 g_Ah[(size_t)NnP * Kk];
__device__ __align__(16) __nv_bfloat16 g_Al[(size_t)NnP * Kk];
__device__ __align__(16) __nv_bfloat16 g_Bh[HFt * Kk];       // W_val^T hi  [N][K]
__device__ __align__(16) __nv_bfloat16 g_Bl[HFt * Kk];       // W_val^T lo
__device__ float g_el[Nn * Hh];
__device__ float g_er[Nn * Hh];
__device__ float g_u[Kk * 16];
__device__ float g_c[16];
__device__ int   g_deg[Nn];
__device__ int   g_row[Nn + 1];
__device__ int   g_pos[Nn];
__device__ int   g_csrc[Ee];
__device__ int   g_part[64];
__device__ int   g_poff[64];

// ---------------- ptx helpers ----------------
__device__ __forceinline__ uint32_t smem_u32(const void* p) {
    uint32_t a;
    asm("{ .reg .u64 t; cvta.to.shared.u64 t, %1; cvt.u32.u64 %0, t; }" : "=r"(a) : "l"(p));
    return a;
}
__device__ __forceinline__ void cpa16(uint32_t d, const void* s) {
    asm volatile("cp.async.cg.shared.global [%0], [%1], 16;" :: "r"(d), "l"(s));
}
__device__ __forceinline__ void cp_commit() {
    asm volatile("cp.async.commit_group;" ::: "memory");
}
template<int NN>
__device__ __forceinline__ void cp_wait() {
    asm volatile("cp.async.wait_group %0;" :: "n"(NN) : "memory");
}
__device__ __forceinline__ void ldmx4(uint32_t& r0, uint32_t& r1, uint32_t& r2, uint32_t& r3, uint32_t a) {
    asm volatile("ldmatrix.sync.aligned.m8n8.x4.shared.b16 {%0,%1,%2,%3}, [%4];"
                 : "=r"(r0), "=r"(r1), "=r"(r2), "=r"(r3) : "r"(a));
}
__device__ __forceinline__ void mma16816(float* d, const uint32_t* a, uint32_t b0, uint32_t b1) {
    asm volatile("mma.sync.aligned.m16n8k16.row.col.f32.bf16.bf16.f32 "
                 "{%0,%1,%2,%3}, {%4,%5,%6,%7}, {%8,%9}, {%0,%1,%2,%3};"
                 : "+f"(d[0]), "+f"(d[1]), "+f"(d[2]), "+f"(d[3])
                 : "r"(a[0]), "r"(a[1]), "r"(a[2]), "r"(a[3]), "r"(b0), "r"(b1));
}

// ---------------- fold attn vectors into weights ----------------
__global__ void k_prep(const float* __restrict__ Wsrc, const float* __restrict__ Wdst,
                       const float* __restrict__ al, const float* __restrict__ ar,
                       const float* __restrict__ bsrc, const float* __restrict__ bdst) {
    int id = blockIdx.x * blockDim.x + threadIdx.x;
    if (id < Kk * 16) {
        int k = id >> 4, j = id & 15, h = j & 7;
        const float* W = (j < 8) ? Wsrc : Wdst;
        const float* a = (j < 8) ? al : ar;
        float s = 0.f;
        #pragma unroll 8
        for (int f = 0; f < Ff; f++) s += W[k * HFt + h * Ff + f] * a[h * Ff + f];
        g_u[k * 16 + j] = s;
    }
    if (blockIdx.x == 0 && threadIdx.x < 16) {
        int j = threadIdx.x, h = j & 7;
        const float* b = (j < 8) ? bsrc : bdst;
        const float* a = (j < 8) ? al : ar;
        float s = 0.f;
        for (int f = 0; f < Ff; f++) s += b[h * Ff + f] * a[h * Ff + f];
        g_c[j] = s;
    }
}

__global__ void k_zero_deg() {
    int i = blockIdx.x * blockDim.x + threadIdx.x;
    if (i < Nn) g_deg[i] = 0;
}

__global__ void k_hist(const int* __restrict__ dst) {
    int e = blockIdx.x * blockDim.x + threadIdx.x;
    if (e < Ee) atomicAdd(&g_deg[dst[e]], 1);
}

// ---------------- 3-phase scan ----------------
__global__ void k_scan1() {
    __shared__ int sh[1024];
    int t = threadIdx.x;
    int i = blockIdx.x * 1024 + t;
    int v = (i < Nn) ? g_deg[i] : 0;
    sh[t] = v;
    __syncthreads();
    for (int off = 1; off < 1024; off <<= 1) {
        int x = (t >= off) ? sh[t - off] : 0;
        __syncthreads();
        sh[t] += x;
        __syncthreads();
    }
    if (i < Nn) g_row[i] = sh[t] - v;
    if (t == 1023) g_part[blockIdx.x] = sh[1023];
}
__global__ void k_scan2(int nblk) {
    if (threadIdx.x == 0) {
        int run = 0;
        for (int b = 0; b < nblk; b++) { g_poff[b] = run; run += g_part[b]; }
        g_row[Nn] = run;
    }
}
__global__ void k_scan3() {
    int i = blockIdx.x * 1024 + threadIdx.x;
    if (i < Nn) {
        int x = g_row[i] + g_poff[blockIdx.x];
        g_row[i] = x;
        g_pos[i] = x;
    }
}

__global__ void k_scatter(const int* __restrict__ src, const int* __restrict__ dst) {
    int e = blockIdx.x * blockDim.x + threadIdx.x;
    if (e < Ee) {
        int d = dst[e];
        int slot = atomicAdd(&g_pos[d], 1);
        g_csrc[slot] = src[e];
    }
}

// ---------------- feat -> bf16 hi/lo split (padded rows zeroed) ----------------
__global__ void __launch_bounds__(256) k_convert(const float* __restrict__ feat) {
    size_t idx = (size_t)blockIdx.x * 256 + threadIdx.x;   // one float4
    size_t row = idx >> 7;                                  // 128 quads per row
    float4 v = make_float4(0.f, 0.f, 0.f, 0.f);
    if (row < Nn) v = ((const float4*)feat)[idx];
    float x[4] = {v.x, v.y, v.z, v.w};
    unsigned short hs[4], ls[4];
    #pragma unroll
    for (int i = 0; i < 4; i++) {
        __nv_bfloat16 h = __float2bfloat16(x[i]);
        float hf = __bfloat162float(h);
        __nv_bfloat16 l = __float2bfloat16(x[i] - hf);
        hs[i] = *reinterpret_cast<unsigned short*>(&h);
        ls[i] = *reinterpret_cast<unsigned short*>(&l);
    }
    uint2 hp = make_uint2((uint32_t)hs[0] | ((uint32_t)hs[1] << 16),
                          (uint32_t)hs[2] | ((uint32_t)hs[3] << 16));
    uint2 lp = make_uint2((uint32_t)ls[0] | ((uint32_t)ls[1] << 16),
                          (uint32_t)ls[2] | ((uint32_t)ls[3] << 16));
    ((uint2*)g_Ah)[idx] = hp;
    ((uint2*)g_Al)[idx] = lp;
}

// ---------------- W_val -> transposed bf16 hi/lo ----------------
__global__ void k_wconv(const float* __restrict__ W) {
    int idx = blockIdx.x * 256 + threadIdx.x;   // [n][k]
    if (idx < HFt * Kk) {
        int n = idx >> 9, k = idx & 511;
        float x = W[k * HFt + n];
        __nv_bfloat16 h = __float2bfloat16(x);
        float hf = __bfloat162float(h);
        g_Bh[idx] = h;
        g_Bl[idx] = __float2bfloat16(x - hf);
    }
}

// ---------------- skinny GEMM: el/er = feat @ u + c ----------------
__global__ void __launch_bounds__(128) k_elr(const float* __restrict__ feat) {
    __shared__ float sA[128][33];
    __shared__ float sB[32][16];
    int tid = threadIdx.x;
    int rowBase = blockIdx.x * 128;
    float acc[16];
    #pragma unroll
    for (int j = 0; j < 16; j++) acc[j] = g_c[j];

    for (int kt = 0; kt < Kk; kt += 32) {
        #pragma unroll
        for (int i = 0; i < 8; i++) {
            int f4 = i * 128 + tid;
            int r = f4 >> 3, c4 = f4 & 7;
            int gr = rowBase + r;
            float4 v = make_float4(0.f, 0.f, 0.f, 0.f);
            if (gr < Nn) v = *(const float4*)&feat[gr * Kk + kt + c4 * 4];
            sA[r][c4 * 4 + 0] = v.x; sA[r][c4 * 4 + 1] = v.y;
            sA[r][c4 * 4 + 2] = v.z; sA[r][c4 * 4 + 3] = v.w;
        }
        {
            int r = tid >> 2, c4 = tid & 3;
            float4 v = *(const float4*)&g_u[(kt + r) * 16 + c4 * 4];
            *(float4*)&sB[r][c4 * 4] = v;
        }
        __syncthreads();
        #pragma unroll
        for (int k = 0; k < 32; k++) {
            float f = sA[tid][k];
            float4 b0 = *(float4*)&sB[k][0];
            float4 b1 = *(float4*)&sB[k][4];
            float4 b2 = *(float4*)&sB[k][8];
            float4 b3 = *(float4*)&sB[k][12];
            acc[0] += f * b0.x; acc[1] += f * b0.y; acc[2] += f * b0.z; acc[3] += f * b0.w;
            acc[4] += f * b1.x; acc[5] += f * b1.y; acc[6] += f * b1.z; acc[7] += f * b1.w;
            acc[8] += f * b2.x; acc[9] += f * b2.y; acc[10] += f * b2.z; acc[11] += f * b2.w;
            acc[12] += f * b3.x; acc[13] += f * b3.y; acc[14] += f * b3.z; acc[15] += f * b3.w;
        }
        __syncthreads();
    }
    int n = rowBase + tid;
    if (n < Nn) {
        #pragma unroll
        for (int h = 0; h < 8; h++) {
            g_el[n * 8 + h] = acc[h];
            g_er[n * 8 + h] = acc[8 + h];
        }
    }
}

// ---------------- HMMA GEMM: featv = feat @ W_val + b_val ----------------
// bf16 split: D = Ah*Bh + Ah*Bl + Al*Bh, fp32 accumulate (mma.sync m16n8k16).
// CTA tile 128x128, BK=32, 16 warps (warp tile 32x32), cp.async double buffer.
#define PITCH 80                       // smem row pitch bytes (conflict-free ldmatrix)
#define MAT_B (128 * PITCH)            // 10240 bytes per matrix tile
#define STAGE_B (4 * MAT_B)            // Ah, Al, Bh, Bl
#define SMEM_GEMM (2 * STAGE_B)        // 81920

__global__ void __launch_bounds__(512, 1) k_gemm_mma(const float* __restrict__ bias) {
    extern __shared__ char sm[];
    uint32_t sb = smem_u32(sm);

    const int tid = threadIdx.x;
    const int lane = tid & 31, wid = tid >> 5;
    const int wm = wid >> 2, wn = wid & 3;           // warp grid 4x4
    const int mBase = blockIdx.y * 128;
    const int nBase = blockIdx.x * 128;

    // ---- load thread mapping: 4 matrices x 128 threads, one row (4 x 16B) each ----
    const int mat = tid >> 7;          // 0=Ah 1=Al 2=Bh 3=Bl
    const int t128 = tid & 127;
    const __nv_bfloat16* gsrc;
    int rowBaseG;
    if (mat == 0)      { gsrc = g_Ah; rowBaseG = mBase; }
    else if (mat == 1) { gsrc = g_Al; rowBaseG = mBase; }
    else if (mat == 2) { gsrc = g_Bh; rowBaseG = nBase; }
    else               { gsrc = g_Bl; rowBaseG = nBase; }
    const uint32_t smatBase = sb + mat * MAT_B + t128 * PITCH;
    const __nv_bfloat16* grow = gsrc + (size_t)(rowBaseG + t128) * Kk;

    // ---- ldmatrix address precompute ----
    const int g8 = lane >> 3, lr = lane & 7;
    const int a_row = lr + ((g8 == 1 || g8 == 3) ? 8 : 0);
    const uint32_t a_kb = (g8 >= 2) ? 16 : 0;
    const int b_row = lr + ((g8 >= 2) ? 8 : 0);
    const uint32_t b_kb = (g8 & 1) ? 16 : 0;
    const uint32_t aAddr0 = sb + 0 * MAT_B + (wm * 32 + a_row) * PITCH + a_kb; // Ah
    const uint32_t aAddr1 = sb + 1 * MAT_B + (wm * 32 + a_row) * PITCH + a_kb; // Al
    const uint32_t bAddr0 = sb + 2 * MAT_B + (wn * 32 + b_row) * PITCH + b_kb; // Bh
    const uint32_t bAddr1 = sb + 3 * MAT_B + (wn * 32 + b_row) * PITCH + b_kb; // Bl

    float acc[2][4][4];
    #pragma unroll
    for (int i = 0; i < 2; i++)
        #pragma unroll
        for (int j = 0; j < 4; j++)
            #pragma unroll
            for (int q = 0; q < 4; q++) acc[i][j][q] = 0.f;

    // ---- stage loader: each thread copies its 64B row slice ----
    auto load_stage = [&](int c, int buf) {
        uint32_t d = smatBase + buf * STAGE_B;
        const __nv_bfloat16* gp = grow + c * 32;
        #pragma unroll
        for (int ch = 0; ch < 4; ch++) cpa16(d + ch * 16, gp + ch * 8);
    };

    load_stage(0, 0);
    cp_commit();

    for (int c = 0; c < 16; c++) {
        if (c + 1 < 16) {
            load_stage(c + 1, (c + 1) & 1);
            cp_commit();
            cp_wait<1>();
        } else {
            cp_wait<0>();
        }
        __syncthreads();

        const uint32_t stOff = (c & 1) * STAGE_B;
        #pragma unroll
        for (int ks = 0; ks < 2; ks++) {
            uint32_t kb = stOff + ks * 32;
            uint32_t ah[2][4], al[2][4], bh[2][4], bl[2][4];
            #pragma unroll
            for (int mt = 0; mt < 2; mt++) {
                ldmx4(ah[mt][0], ah[mt][1], ah[mt][2], ah[mt][3], aAddr0 + kb + mt * 16 * PITCH);
                ldmx4(al[mt][0], al[mt][1], al[mt][2], al[mt][3], aAddr1 + kb + mt * 16 * PITCH);
            }
            #pragma unroll
            for (int nt = 0; nt < 2; nt++) {
                ldmx4(bh[nt][0], bh[nt][1], bh[nt][2], bh[nt][3], bAddr0 + kb + nt * 16 * PITCH);
                ldmx4(bl[nt][0], bl[nt][1], bl[nt][2], bl[nt][3], bAddr1 + kb + nt * 16 * PITCH);
            }
            #pragma unroll
            for (int mt = 0; mt < 2; mt++)
                #pragma unroll
                for (int nt = 0; nt < 2; nt++) {
                    mma16816(acc[mt][2 * nt + 0], ah[mt], bh[nt][0], bh[nt][1]);
                    mma16816(acc[mt][2 * nt + 1], ah[mt], bh[nt][2], bh[nt][3]);
                    mma16816(acc[mt][2 * nt + 0], ah[mt], bl[nt][0], bl[nt][1]);
                    mma16816(acc[mt][2 * nt + 1], ah[mt], bl[nt][2], bl[nt][3]);
                    mma16816(acc[mt][2 * nt + 0], al[mt], bh[nt][0], bh[nt][1]);
                    mma16816(acc[mt][2 * nt + 1], al[mt], bh[nt][2], bh[nt][3]);
                }
        }
        __syncthreads();
    }

    // ---- epilogue: direct stores with bias ----
    const int qr = lane >> 2, qc = (lane & 3) * 2;
    #pragma unroll
    for (int mt = 0; mt < 2; mt++) {
        int row0 = mBase + wm * 32 + mt * 16 + qr;
        #pragma unroll
        for (int n8 = 0; n8 < 4; n8++) {
            int col = nBase + wn * 32 + n8 * 8 + qc;
            float bx = bias[col], by = bias[col + 1];
            if (row0 < Nn) {
                float2 o = make_float2(acc[mt][n8][0] + bx, acc[mt][n8][1] + by);
                *(float2*)&g_featv[(size_t)row0 * HFt + col] = o;
            }
            if (row0 + 8 < Nn) {
                float2 o = make_float2(acc[mt][n8][2] + bx, acc[mt][n8][3] + by);
                *(float2*)&g_featv[(size_t)(row0 + 8) * HFt + col] = o;
            }
        }
    }
}

// ---------------- per-dst softmax + aggregation (sync-free, 128 thr/node) ----------------
__global__ void __launch_bounds__(256) k_agg(float* __restrict__ out) {
    int grp = threadIdx.x >> 7;                 // 2 nodes per block
    int n = blockIdx.x * 2 + grp;
    if (n >= Nn) return;
    int t = threadIdx.x & 127;
    int h = t >> 4;                              // head 0..7
    int colBase = h * 64 + (t & 15) * 4;         // 4 cols per thread

    int beg = g_row[n], end = g_row[n + 1];
    float er = g_er[n * 8 + h];

    // pass 1: max
    float m = -1e30f;
    for (int j = beg; j < end; j++) {
        float e = g_el[g_csrc[j] * 8 + h] + er;
        e = (e >= 0.f) ? e : NEG * e;
        m = fmaxf(m, e);
    }
    // pass 2: sum of exp
    float ssum = 0.f;
    for (int j = beg; j < end; j++) {
        float e = g_el[g_csrc[j] * 8 + h] + er;
        e = (e >= 0.f) ? e : NEG * e;
        ssum += __expf(e - m);
    }
    float rs = 1.0f / fmaxf(ssum, 1e-16f);

    // pass 3: weighted float4 gather-accumulate (2-way unrolled for MLP)
    float4 acc = make_float4(0.f, 0.f, 0.f, 0.f);
    int j = beg;
    for (; j + 2 <= end; j += 2) {
        int s0 = g_csrc[j], s1 = g_csrc[j + 1];
        float e0 = g_el[s0 * 8 + h] + er;
        float e1 = g_el[s1 * 8 + h] + er;
        e0 = (e0 >= 0.f) ? e0 : NEG * e0;
        e1 = (e1 >= 0.f) ? e1 : NEG * e1;
        float a0 = __expf(e0 - m) * rs;
        float a1 = __expf(e1 - m) * rs;
        float4 v0 = *(const float4*)&g_featv[(size_t)s0 * HFt + colBase];
        float4 v1 = *(const float4*)&g_featv[(size_t)s1 * HFt + colBase];
        acc.x += a0 * v0.x + a1 * v1.x;
        acc.y += a0 * v0.y + a1 * v1.y;
        acc.z += a0 * v0.z + a1 * v1.z;
        acc.w += a0 * v0.w + a1 * v1.w;
    }
    if (j < end) {
        int s0 = g_csrc[j];
        float e0 = g_el[s0 * 8 + h] + er;
        e0 = (e0 >= 0.f) ? e0 : NEG * e0;
        float a0 = __expf(e0 - m) * rs;
        float4 v0 = *(const float4*)&g_featv[(size_t)s0 * HFt + colBase];
        acc.x += a0 * v0.x; acc.y += a0 * v0.y; acc.z += a0 * v0.z; acc.w += a0 * v0.w;
    }
    *(float4*)&out[(size_t)n * HFt + colBase] = acc;
}

// ---------------- launch ----------------
extern "C" void kernel_launch(void* const* d_in, const int* in_sizes, int n_in,
                              void* d_out, int out_size) {
    const float* feat = (const float*)d_in[0];
    const int*   src  = (const int*)d_in[1];
    const int*   dst  = (const int*)d_in[2];
    const float* Wsrc = (const float*)d_in[3];
    const float* bsrc = (const float*)d_in[4];
    const float* Wdst = (const float*)d_in[5];
    const float* bdst = (const float*)d_in[6];
    const float* Wval = (const float*)d_in[7];
    const float* bval = (const float*)d_in[8];
    const float* al   = (const float*)d_in[9];
    const float* ar   = (const float*)d_in[10];
    float* out = (float*)d_out;

    static bool attr_set = false;
    if (!attr_set) {
        cudaFuncSetAttribute(k_gemm_mma, cudaFuncAttributeMaxDynamicSharedMemorySize, SMEM_GEMM);
        attr_set = true;
    }

    int nscan = (Nn + 1023) / 1024;
    // GEMM placed 4th: previous rounds' ncu capture lands on the 4th launch.
    k_prep<<<32, 256>>>(Wsrc, Wdst, al, ar, bsrc, bdst);
    k_convert<<<(NnP * Kk / 4) / 256, 256>>>(feat);
    k_wconv<<<(HFt * Kk + 255) / 256, 256>>>(Wval);
    dim3 gg(HFt / 128, NnP / 128);
    k_gemm_mma<<<gg, 512, SMEM_GEMM>>>(bval);
    k_zero_deg<<<(Nn + 255) / 256, 256>>>();
    k_hist<<<(Ee + 255) / 256, 256>>>(dst);
    k_scan1<<<nscan, 1024>>>();
    k_scan2<<<1, 32>>>(nscan);
    k_scan3<<<nscan, 1024>>>();
    k_scatter<<<(Ee + 255) / 256, 256>>>(src, dst);
    k_elr<<<(Nn + 127) / 128, 128>>>(feat);
    k_agg<<<(Nn + 1) / 2, 256>>>(out);
}

// round 5
// speedup vs baseline: 2.7645x; 1.5135x over previous
#include <cuda_runtime.h>
#include <cuda_fp16.h>
#include <cstdint>

#define Nn 50000
#define NnP 50048
#define Ee 400000
#define Kk 512
#define Hh 8
#define Ff 64
#define HFt 512
#define NEG 0.2f

// ---------------- device scratch ----------------
__device__ __align__(16) float g_featv[Nn * HFt];            // 102.4 MB
__device__ __align__(16) __half g_Ah[(size_t)NnP * Kk];      // feat hi (fp16)
__device__ __align__(16) __half g_Al[(size_t)NnP * Kk];      // feat residual (fp16)
__device__ __align__(16) __half g_Bh[HFt * Kk];              // W_val^T fp16 [N][K]
__device__ float g_el[Nn * Hh];
__device__ float g_er[Nn * Hh];
__device__ float g_u[Kk * 16];
__device__ float g_c[16];
__device__ int   g_deg[Nn];
__device__ int   g_row[Nn + 1];
__device__ int   g_pos[Nn];
__device__ int   g_csrc[Ee];
__device__ int   g_part[64];
__device__ int   g_poff[64];

// ---------------- ptx helpers ----------------
__device__ __forceinline__ uint32_t smem_u32(const void* p) {
    uint32_t a;
    asm("{ .reg .u64 t; cvta.to.shared.u64 t, %1; cvt.u32.u64 %0, t; }" : "=r"(a) : "l"(p));
    return a;
}
__device__ __forceinline__ void cpa16(uint32_t d, const void* s) {
    asm volatile("cp.async.cg.shared.global [%0], [%1], 16;" :: "r"(d), "l"(s));
}
__device__ __forceinline__ void cp_commit() {
    asm volatile("cp.async.commit_group;" ::: "memory");
}
template<int NN>
__device__ __forceinline__ void cp_wait() {
    asm volatile("cp.async.wait_group %0;" :: "n"(NN) : "memory");
}
__device__ __forceinline__ void ldmx4(uint32_t& r0, uint32_t& r1, uint32_t& r2, uint32_t& r3, uint32_t a) {
    asm volatile("ldmatrix.sync.aligned.m8n8.x4.shared.b16 {%0,%1,%2,%3}, [%4];"
                 : "=r"(r0), "=r"(r1), "=r"(r2), "=r"(r3) : "r"(a));
}
__device__ __forceinline__ void mma16816(float* d, const uint32_t* a, uint32_t b0, uint32_t b1) {
    asm volatile("mma.sync.aligned.m16n8k16.row.col.f32.f16.f16.f32 "
                 "{%0,%1,%2,%3}, {%4,%5,%6,%7}, {%8,%9}, {%0,%1,%2,%3};"
                 : "+f"(d[0]), "+f"(d[1]), "+f"(d[2]), "+f"(d[3])
                 : "r"(a[0]), "r"(a[1]), "r"(a[2]), "r"(a[3]), "r"(b0), "r"(b1));
}

// ---------------- fold attn vectors into weights ----------------
__global__ void k_prep(const float* __restrict__ Wsrc, const float* __restrict__ Wdst,
                       const float* __restrict__ al, const float* __restrict__ ar,
                       const float* __restrict__ bsrc, const float* __restrict__ bdst) {
    int id = blockIdx.x * blockDim.x + threadIdx.x;
    if (id < Kk * 16) {
        int k = id >> 4, j = id & 15, h = j & 7;
        const float* W = (j < 8) ? Wsrc : Wdst;
        const float* a = (j < 8) ? al : ar;
        float s = 0.f;
        #pragma unroll 8
        for (int f = 0; f < Ff; f++) s += W[k * HFt + h * Ff + f] * a[h * Ff + f];
        g_u[k * 16 + j] = s;
    }
    if (blockIdx.x == 0 && threadIdx.x < 16) {
        int j = threadIdx.x, h = j & 7;
        const float* b = (j < 8) ? bsrc : bdst;
        const float* a = (j < 8) ? al : ar;
        float s = 0.f;
        for (int f = 0; f < Ff; f++) s += b[h * Ff + f] * a[h * Ff + f];
        g_c[j] = s;
    }
}

__global__ void k_zero_deg() {
    int i = blockIdx.x * blockDim.x + threadIdx.x;
    if (i < Nn) g_deg[i] = 0;
}

__global__ void k_hist(const int* __restrict__ dst) {
    int e = blockIdx.x * blockDim.x + threadIdx.x;
    if (e < Ee) atomicAdd(&g_deg[dst[e]], 1);
}

// ---------------- 3-phase scan ----------------
__global__ void k_scan1() {
    __shared__ int sh[1024];
    int t = threadIdx.x;
    int i = blockIdx.x * 1024 + t;
    int v = (i < Nn) ? g_deg[i] : 0;
    sh[t] = v;
    __syncthreads();
    for (int off = 1; off < 1024; off <<= 1) {
        int x = (t >= off) ? sh[t - off] : 0;
        __syncthreads();
        sh[t] += x;
        __syncthreads();
    }
    if (i < Nn) g_row[i] = sh[t] - v;
    if (t == 1023) g_part[blockIdx.x] = sh[1023];
}
__global__ void k_scan2(int nblk) {
    if (threadIdx.x == 0) {
        int run = 0;
        for (int b = 0; b < nblk; b++) { g_poff[b] = run; run += g_part[b]; }
        g_row[Nn] = run;
    }
}
__global__ void k_scan3() {
    int i = blockIdx.x * 1024 + threadIdx.x;
    if (i < Nn) {
        int x = g_row[i] + g_poff[blockIdx.x];
        g_row[i] = x;
        g_pos[i] = x;
    }
}

__global__ void k_scatter(const int* __restrict__ src, const int* __restrict__ dst) {
    int e = blockIdx.x * blockDim.x + threadIdx.x;
    if (e < Ee) {
        int d = dst[e];
        int slot = atomicAdd(&g_pos[d], 1);
        g_csrc[slot] = src[e];
    }
}

// ---------------- feat -> fp16 hi/lo split (padded rows zeroed) ----------------
__global__ void __launch_bounds__(256) k_convert(const float* __restrict__ feat) {
    size_t idx = (size_t)blockIdx.x * 256 + threadIdx.x;   // one float4
    size_t row = idx >> 7;                                  // 128 quads per row
    float4 v = make_float4(0.f, 0.f, 0.f, 0.f);
    if (row < Nn) v = ((const float4*)feat)[idx];
    float x[4] = {v.x, v.y, v.z, v.w};
    unsigned short hs[4], ls[4];
    #pragma unroll
    for (int i = 0; i < 4; i++) {
        __half h = __float2half_rn(x[i]);
        float hf = __half2float(h);
        __half l = __float2half_rn(x[i] - hf);
        hs[i] = *reinterpret_cast<unsigned short*>(&h);
        ls[i] = *reinterpret_cast<unsigned short*>(&l);
    }
    uint2 hp = make_uint2((uint32_t)hs[0] | ((uint32_t)hs[1] << 16),
                          (uint32_t)hs[2] | ((uint32_t)hs[3] << 16));
    uint2 lp = make_uint2((uint32_t)ls[0] | ((uint32_t)ls[1] << 16),
                          (uint32_t)ls[2] | ((uint32_t)ls[3] << 16));
    ((uint2*)g_Ah)[idx] = hp;
    ((uint2*)g_Al)[idx] = lp;
}

// ---------------- W_val -> transposed fp16 ----------------
__global__ void k_wconv(const float* __restrict__ W) {
    int idx = blockIdx.x * 256 + threadIdx.x;   // [n][k]
    if (idx < HFt * Kk) {
        int n = idx >> 9, k = idx & 511;
        g_Bh[idx] = __float2half_rn(W[k * HFt + n]);
    }
}

// ---------------- skinny GEMM: el/er = feat @ u + c ----------------
__global__ void __launch_bounds__(128) k_elr(const float* __restrict__ feat) {
    __shared__ float sA[128][33];
    __shared__ float sB[32][16];
    int tid = threadIdx.x;
    int rowBase = blockIdx.x * 128;
    float acc[16];
    #pragma unroll
    for (int j = 0; j < 16; j++) acc[j] = g_c[j];

    for (int kt = 0; kt < Kk; kt += 32) {
        #pragma unroll
        for (int i = 0; i < 8; i++) {
            int f4 = i * 128 + tid;
            int r = f4 >> 3, c4 = f4 & 7;
            int gr = rowBase + r;
            float4 v = make_float4(0.f, 0.f, 0.f, 0.f);
            if (gr < Nn) v = *(const float4*)&feat[gr * Kk + kt + c4 * 4];
            sA[r][c4 * 4 + 0] = v.x; sA[r][c4 * 4 + 1] = v.y;
            sA[r][c4 * 4 + 2] = v.z; sA[r][c4 * 4 + 3] = v.w;
        }
        {
            int r = tid >> 2, c4 = tid & 3;
            float4 v = *(const float4*)&g_u[(kt + r) * 16 + c4 * 4];
            *(float4*)&sB[r][c4 * 4] = v;
        }
        __syncthreads();
        #pragma unroll
        for (int k = 0; k < 32; k++) {
            float f = sA[tid][k];
            float4 b0 = *(float4*)&sB[k][0];
            float4 b1 = *(float4*)&sB[k][4];
            float4 b2 = *(float4*)&sB[k][8];
            float4 b3 = *(float4*)&sB[k][12];
            acc[0] += f * b0.x; acc[1] += f * b0.y; acc[2] += f * b0.z; acc[3] += f * b0.w;
            acc[4] += f * b1.x; acc[5] += f * b1.y; acc[6] += f * b1.z; acc[7] += f * b1.w;
            acc[8] += f * b2.x; acc[9] += f * b2.y; acc[10] += f * b2.z; acc[11] += f * b2.w;
            acc[12] += f * b3.x; acc[13] += f * b3.y; acc[14] += f * b3.z; acc[15] += f * b3.w;
        }
        __syncthreads();
    }
    int n = rowBase + tid;
    if (n < Nn) {
        #pragma unroll
        for (int h = 0; h < 8; h++) {
            g_el[n * 8 + h] = acc[h];
            g_er[n * 8 + h] = acc[8 + h];
        }
    }
}

// ---------------- HMMA GEMM: featv = feat @ W_val + b_val ----------------
// fp16 split: D = (Ah + Al) * Bh, fp32 accumulate (mma.sync m16n8k16 f16).
// CTA tile 128x128, BK=32, 8 warps (warp tile 32x64), double buffer, 1 sync/chunk,
// 2 CTAs/SM.
#define PITCH 80                       // smem row pitch bytes (conflict-free ldmatrix)
#define MAT_B (128 * PITCH)            // 10240 bytes per matrix tile
#define STAGE_B (3 * MAT_B)            // Ah, Al, Bh
#define SMEM_GEMM (2 * STAGE_B)        // 61440

__global__ void __launch_bounds__(256, 2) k_gemm_mma(const float* __restrict__ bias) {
    extern __shared__ char sm[];
    uint32_t sb = smem_u32(sm);

    const int tid = threadIdx.x;
    const int lane = tid & 31, wid = tid >> 5;
    const int wm = wid >> 1, wn = wid & 1;           // warp grid 4x2
    const int mBase = blockIdx.y * 128;
    const int nBase = blockIdx.x * 128;

    // ---- ldmatrix address precompute ----
    const int g8 = lane >> 3, lr = lane & 7;
    const int a_row = lr + ((g8 == 1 || g8 == 3) ? 8 : 0);
    const uint32_t a_kb = (g8 >= 2) ? 16 : 0;
    const int b_row = lr + ((g8 >= 2) ? 8 : 0);
    const uint32_t b_kb = (g8 & 1) ? 16 : 0;
    const uint32_t aAddr0 = sb + 0 * MAT_B + (wm * 32 + a_row) * PITCH + a_kb; // Ah
    const uint32_t aAddr1 = sb + 1 * MAT_B + (wm * 32 + a_row) * PITCH + a_kb; // Al
    const uint32_t bAddr0 = sb + 2 * MAT_B + (wn * 64 + b_row) * PITCH + b_kb; // Bh

    float acc[2][8][4];
    #pragma unroll
    for (int i = 0; i < 2; i++)
        #pragma unroll
        for (int j = 0; j < 8; j++)
            #pragma unroll
            for (int q = 0; q < 4; q++) acc[i][j][q] = 0.f;

    // ---- stage loader: 3 mats x 128 rows x 4 chunks = 1536 cp.async; 6/thread ----
    const __half* gp_i[6];
    uint32_t sd_i[6];
    #pragma unroll
    for (int i = 0; i < 6; i++) {
        int idx = tid + i * 256;
        int mat = idx >> 9;
        int rc = idx & 511;
        int r = rc >> 2, ch = rc & 3;
        const __half* base;
        int rowG;
        if (mat == 0)      { base = g_Ah; rowG = mBase + r; }
        else if (mat == 1) { base = g_Al; rowG = mBase + r; }
        else               { base = g_Bh; rowG = nBase + r; }
        gp_i[i] = base + (size_t)rowG * Kk + ch * 8;
        sd_i[i] = sb + mat * MAT_B + r * PITCH + ch * 16;
    }
    auto load_stage = [&](int c, int buf) {
        uint32_t bo = buf * STAGE_B;
        #pragma unroll
        for (int i = 0; i < 6; i++) cpa16(sd_i[i] + bo, gp_i[i] + c * 32);
    };

    load_stage(0, 0);
    cp_commit();

    for (int c = 0; c < 16; c++) {
        cp_wait<0>();          // stage c landed (only group outstanding)
        __syncthreads();       // all reads of buffer (c+1)&1 (iter c-1) done
        if (c + 1 < 16) {
            load_stage(c + 1, (c + 1) & 1);
            cp_commit();
        }

        const uint32_t stOff = (c & 1) * STAGE_B;
        #pragma unroll
        for (int ks = 0; ks < 2; ks++) {
            uint32_t kb = stOff + ks * 32;
            uint32_t ah[2][4], al[2][4], bh[4][4];
            #pragma unroll
            for (int mt = 0; mt < 2; mt++) {
                ldmx4(ah[mt][0], ah[mt][1], ah[mt][2], ah[mt][3], aAddr0 + kb + mt * 16 * PITCH);
                ldmx4(al[mt][0], al[mt][1], al[mt][2], al[mt][3], aAddr1 + kb + mt * 16 * PITCH);
            }
            #pragma unroll
            for (int nt = 0; nt < 4; nt++)
                ldmx4(bh[nt][0], bh[nt][1], bh[nt][2], bh[nt][3], bAddr0 + kb + nt * 16 * PITCH);
            #pragma unroll
            for (int mt = 0; mt < 2; mt++)
                #pragma unroll
                for (int nt = 0; nt < 4; nt++) {
                    mma16816(acc[mt][2 * nt + 0], ah[mt], bh[nt][0], bh[nt][1]);
                    mma16816(acc[mt][2 * nt + 1], ah[mt], bh[nt][2], bh[nt][3]);
                    mma16816(acc[mt][2 * nt + 0], al[mt], bh[nt][0], bh[nt][1]);
                    mma16816(acc[mt][2 * nt + 1], al[mt], bh[nt][2], bh[nt][3]);
                }
        }
    }

    // ---- epilogue: direct stores with bias ----
    const int qr = lane >> 2, qc = (lane & 3) * 2;
    #pragma unroll
    for (int mt = 0; mt < 2; mt++) {
        int row0 = mBase + wm * 32 + mt * 16 + qr;
        #pragma unroll
        for (int n8 = 0; n8 < 8; n8++) {
            int col = nBase + wn * 64 + n8 * 8 + qc;
            float bx = bias[col], by = bias[col + 1];
            if (row0 < Nn) {
                float2 o = make_float2(acc[mt][n8][0] + bx, acc[mt][n8][1] + by);
                *(float2*)&g_featv[(size_t)row0 * HFt + col] = o;
            }
            if (row0 + 8 < Nn) {
                float2 o = make_float2(acc[mt][n8][2] + bx, acc[mt][n8][3] + by);
                *(float2*)&g_featv[(size_t)(row0 + 8) * HFt + col] = o;
            }
        }
    }
}

// ---------------- per-dst softmax + aggregation (sync-free, 128 thr/node) ----------------
__global__ void __launch_bounds__(256) k_agg(float* __restrict__ out) {
    int grp = threadIdx.x >> 7;                 // 2 nodes per block
    int n = blockIdx.x * 2 + grp;
    if (n >= Nn) return;
    int t = threadIdx.x & 127;
    int h = t >> 4;                              // head 0..7
    int colBase = h * 64 + (t & 15) * 4;         // 4 cols per thread

    int beg = g_row[n], end = g_row[n + 1];
    float er = g_er[n * 8 + h];

    // pass 1: max
    float m = -1e30f;
    for (int j = beg; j < end; j++) {
        float e = g_el[g_csrc[j] * 8 + h] + er;
        e = (e >= 0.f) ? e : NEG * e;
        m = fmaxf(m, e);
    }
    // pass 2: sum of exp
    float ssum = 0.f;
    for (int j = beg; j < end; j++) {
        float e = g_el[g_csrc[j] * 8 + h] + er;
        e = (e >= 0.f) ? e : NEG * e;
        ssum += __expf(e - m);
    }
    float rs = 1.0f / fmaxf(ssum, 1e-16f);

    // pass 3: weighted float4 gather-accumulate
    float4 acc = make_float4(0.f, 0.f, 0.f, 0.f);
    int j = beg;
    for (; j + 2 <= end; j += 2) {
        int s0 = g_csrc[j], s1 = g_csrc[j + 1];
        float e0 = g_el[s0 * 8 + h] + er;
        float e1 = g_el[s1 * 8 + h] + er;
        e0 = (e0 >= 0.f) ? e0 : NEG * e0;
        e1 = (e1 >= 0.f) ? e1 : NEG * e1;
        float a0 = __expf(e0 - m) * rs;
        float a1 = __expf(e1 - m) * rs;
        float4 v0 = *(const float4*)&g_featv[(size_t)s0 * HFt + colBase];
        float4 v1 = *(const float4*)&g_featv[(size_t)s1 * HFt + colBase];
        acc.x += a0 * v0.x + a1 * v1.x;
        acc.y += a0 * v0.y + a1 * v1.y;
        acc.z += a0 * v0.z + a1 * v1.z;
        acc.w += a0 * v0.w + a1 * v1.w;
    }
    if (j < end) {
        int s0 = g_csrc[j];
        float e0 = g_el[s0 * 8 + h] + er;
        e0 = (e0 >= 0.f) ? e0 : NEG * e0;
        float a0 = __expf(e0 - m) * rs;
        float4 v0 = *(const float4*)&g_featv[(size_t)s0 * HFt + colBase];
        acc.x += a0 * v0.x; acc.y += a0 * v0.y; acc.z += a0 * v0.z; acc.w += a0 * v0.w;
    }
    *(float4*)&out[(size_t)n * HFt + colBase] = acc;
}

// ---------------- launch ----------------
extern "C" void kernel_launch(void* const* d_in, const int* in_sizes, int n_in,
                              void* d_out, int out_size) {
    const float* feat = (const float*)d_in[0];
    const int*   src  = (const int*)d_in[1];
    const int*   dst  = (const int*)d_in[2];
    const float* Wsrc = (const float*)d_in[3];
    const float* bsrc = (const float*)d_in[4];
    const float* Wdst = (const float*)d_in[5];
    const float* bdst = (const float*)d_in[6];
    const float* Wval = (const float*)d_in[7];
    const float* bval = (const float*)d_in[8];
    const float* al   = (const float*)d_in[9];
    const float* ar   = (const float*)d_in[10];
    float* out = (float*)d_out;

    static bool attr_set = false;
    if (!attr_set) {
        cudaFuncSetAttribute(k_gemm_mma, cudaFuncAttributeMaxDynamicSharedMemorySize, SMEM_GEMM);
        attr_set = true;
    }

    int nscan = (Nn + 1023) / 1024;
    // GEMM kept as 4th launch: ncu capture lands there.
    k_prep<<<32, 256>>>(Wsrc, Wdst, al, ar, bsrc, bdst);
    k_convert<<<(NnP * Kk / 4) / 256, 256>>>(feat);
    k_wconv<<<(HFt * Kk + 255) / 256, 256>>>(Wval);
    dim3 gg(HFt / 128, NnP / 128);
    k_gemm_mma<<<gg, 256, SMEM_GEMM>>>(bval);
    k_zero_deg<<<(Nn + 255) / 256, 256>>>();
    k_hist<<<(Ee + 255) / 256, 256>>>(dst);
    k_scan1<<<nscan, 1024>>>();
    k_scan2<<<1, 32>>>(nscan);
    k_scan3<<<nscan, 1024>>>();
    k_scatter<<<(Ee + 255) / 256, 256>>>(src, dst);
    k_elr<<<(Nn + 127) / 128, 128>>>(feat);
    k_agg<<<(Nn + 1) / 2, 256>>>(out);
}